// round 8
// baseline (speedup 1.0000x reference)
#include <cuda_runtime.h>
#include <cuda_bf16.h>
#include <cstdint>

// Static scratch (no allocations allowed).
// Fixed-capacity bucket table: 32 slots per vertex. With ids ~ Poisson(6),
// P(any vertex degree > 32) ~ 4e-25 — and the fill guard keeps memory safe
// regardless. Sized for V <= 4M.
#define SLOT_CAP   32
#define SLOT_SHIFT 5
__device__ int g_counts[4u << 20];               // per-vertex valence
__device__ int g_slots[(4u << 20) * SLOT_CAP];   // edge ids, bucket per vertex

// ---------------------------------------------------------------------------
// Pass 1: single-pass inverse-map build. One returning atomic + one scattered
// store per edge (same cost as the old perm pass), but no histogram and no
// prefix scan are needed because buckets have fixed capacity.
// ---------------------------------------------------------------------------
__global__ void fill_kernel(const int* __restrict__ ids, int n)
{
    int i = blockIdx.x * blockDim.x + threadIdx.x;
    if (i < n) {
        int v = __ldg(ids + i);
        int pos = atomicAdd(&g_counts[v], 1);
        if (pos < SLOT_CAP)                       // safety guard (never taken)
            g_slots[(v << SLOT_SHIFT) + pos] = i;
    }
}

// ---------------------------------------------------------------------------
// Pass 2: gather + mean. 8 threads per vertex; thread s covers feature quad s
// as one float4 (the 8-thread group covers one 128B edge row per load).
// Per 8-edge chunk each thread loads all 8 slot entries (1 fetch + 7
// L1-broadcast hits) so the row-load address chain is load->load.
// All 8 row loads are independent -> high MLP; no serial tail for deg <= 8
// (~85% of Poisson(6) vertices).
// ---------------------------------------------------------------------------
__global__ void gather_kernel(const float4* __restrict__ x4,
                              float4* __restrict__ out4, int V)
{
    long long t = (long long)blockIdx.x * blockDim.x + threadIdx.x;
    int v = (int)(t >> 3);          // vertex
    int s = (int)(t & 7);           // quad index within the 32-dim row
    if (v >= V) return;

    int deg = __ldg(&g_counts[v]);
    int cap = (deg < SLOT_CAP) ? deg : SLOT_CAP;
    const int* slots = g_slots + ((long long)v << SLOT_SHIFT);

    float4 acc = make_float4(0.f, 0.f, 0.f, 0.f);

    for (int base = 0; base < cap; base += 8) {
        int e[8];
        #pragma unroll
        for (int u = 0; u < 8; u++) {
            int j = base + u;
            e[u] = (j < cap) ? __ldg(slots + j) : -1;
        }
        #pragma unroll
        for (int u = 0; u < 8; u++) {
            if (e[u] >= 0) {
                float4 a = __ldg(x4 + (long long)e[u] * 8 + s);
                acc.x += a.x; acc.y += a.y; acc.z += a.z; acc.w += a.w;
            }
        }
    }

    float inv = 1.0f / fmaxf((float)deg, 1.0f);
    out4[(long long)v * 8 + s] =
        make_float4(acc.x * inv, acc.y * inv, acc.z * inv, acc.w * inv);
}

extern "C" void kernel_launch(void* const* d_in, const int* in_sizes, int n_in,
                              void* d_out, int out_size)
{
    const float4* x4  = (const float4*)d_in[0];
    const int*    ids = (const int*)d_in[1];

    int n_he = in_sizes[1];                     // element count of vertex_ids
    int V    = (int)((long long)out_size / 32); // output is [V, 32]

    // Zero the valence counters (slots need no clearing — counts gate reads).
    void* counts_ptr = nullptr;
    cudaGetSymbolAddress(&counts_ptr, g_counts);
    cudaMemsetAsync(counts_ptr, 0, (size_t)V * sizeof(int));

    // Pass 1: bucket fill (single pass, no histogram/scan).
    fill_kernel<<<(n_he + 255) / 256, 256>>>(ids, n_he);

    // Pass 2: gather + mean, 8 threads per vertex.
    {
        long long total = (long long)V * 8;
        int threads = 256;
        int blocks = (int)((total + threads - 1) / threads);
        gather_kernel<<<blocks, threads>>>(x4, (float4*)d_out, V);
    }
}

// round 9
// speedup vs baseline: 1.1378x; 1.1378x over previous
#include <cuda_runtime.h>
#include <cuda_bf16.h>
#include <cstdint>

// Static scratch (no allocations allowed). Sized for V <= 4M, n_he <= 8M.
__device__ int g_counts[4u << 20];      // histogram / per-vertex valence
__device__ int g_offsets[4u << 20];     // block-local exclusive offsets
__device__ int g_blocksums[4096];       // global exclusive block offsets
__device__ int g_rank[8u << 20];        // within-vertex rank of each edge
__device__ int g_perm[8u << 20];        // edge indices grouped by vertex (dense)

// ---------------------------------------------------------------------------
// Warp-shuffle inclusive scan helper.
// ---------------------------------------------------------------------------
__device__ __forceinline__ int warp_incl_scan(int v)
{
    #pragma unroll
    for (int d = 1; d < 32; d <<= 1) {
        int t = __shfl_up_sync(0xffffffffu, v, d);
        if ((threadIdx.x & 31) >= d) v += t;
    }
    return v;
}

// ---------------------------------------------------------------------------
// Pass A: histogram + per-edge rank. The atomic return value (the edge's
// within-vertex rank) is kept and written coalesced (int4), so the later
// placement pass needs NO atomics at all.
// ---------------------------------------------------------------------------
__global__ void rank_hist_kernel(const int4* __restrict__ ids4, int nq,
                                 const int* __restrict__ ids, int n)
{
    int i = blockIdx.x * blockDim.x + threadIdx.x;
    if (i < nq) {
        int4 v = __ldg(ids4 + i);
        int4 r;
        r.x = atomicAdd(&g_counts[v.x], 1);
        r.y = atomicAdd(&g_counts[v.y], 1);
        r.z = atomicAdd(&g_counts[v.z], 1);
        r.w = atomicAdd(&g_counts[v.w], 1);
        ((int4*)g_rank)[i] = r;
    }
    if (i == 0) {
        for (int j = nq * 4; j < n; j++)
            g_rank[j] = atomicAdd(&g_counts[__ldg(ids + j)], 1);
    }
}

// ---------------------------------------------------------------------------
// Scan step 1: per-block (1024) exclusive scan of counts; block totals out.
// g_offsets gets BLOCK-LOCAL exclusive offsets.
// ---------------------------------------------------------------------------
__global__ void scan1_kernel(int V)
{
    __shared__ int wsum[32];
    int i = blockIdx.x * 1024 + threadIdx.x;
    int v = (i < V) ? g_counts[i] : 0;
    int incl = warp_incl_scan(v);
    int lane = threadIdx.x & 31, wid = threadIdx.x >> 5;
    if (lane == 31) wsum[wid] = incl;
    __syncthreads();
    if (wid == 0) {
        int w = wsum[lane];
        int ws = warp_incl_scan(w);
        wsum[lane] = ws - w;                  // exclusive warp offsets
    }
    __syncthreads();
    int excl = incl - v + wsum[wid];
    if (i < V) g_offsets[i] = excl;
    if (threadIdx.x == 1023) g_blocksums[blockIdx.x] = excl + v;   // block total
}

// ---------------------------------------------------------------------------
// Scan step 2: single-block exclusive scan of block sums (carry loop).
// ---------------------------------------------------------------------------
__global__ void scan2_kernel(int nb)
{
    __shared__ int wsum[32];
    __shared__ int carry_s;
    if (threadIdx.x == 0) carry_s = 0;
    __syncthreads();
    for (int base = 0; base < nb; base += 1024) {
        int i = base + threadIdx.x;
        int v = (i < nb) ? g_blocksums[i] : 0;
        int incl = warp_incl_scan(v);
        int lane = threadIdx.x & 31, wid = threadIdx.x >> 5;
        if (lane == 31) wsum[wid] = incl;
        __syncthreads();
        if (wid == 0) {
            int w = wsum[lane];
            int ws = warp_incl_scan(w);
            wsum[lane] = ws - w;
        }
        __syncthreads();
        int excl = incl - v + wsum[wid] + carry_s;
        if (i < nb) g_blocksums[i] = excl;
        __syncthreads();
        if (threadIdx.x == 1023) carry_s = excl + v;
        __syncthreads();
    }
}

// ---------------------------------------------------------------------------
// Pass B: atomic-free placement. pos = global offset of v + precomputed rank.
// ids and ranks stream from L2 (both just touched); only the 24 MB scattered
// perm store pays.
// ---------------------------------------------------------------------------
__global__ void place_kernel(const int4* __restrict__ ids4, int nq,
                             const int* __restrict__ ids, int n)
{
    int i = blockIdx.x * blockDim.x + threadIdx.x;
    if (i < nq) {
        int4 v = __ldg(ids4 + i);
        int4 r = __ldg(((const int4*)g_rank) + i);
        int p0 = __ldg(&g_offsets[v.x]) + __ldg(&g_blocksums[v.x >> 10]) + r.x;
        int p1 = __ldg(&g_offsets[v.y]) + __ldg(&g_blocksums[v.y >> 10]) + r.y;
        int p2 = __ldg(&g_offsets[v.z]) + __ldg(&g_blocksums[v.z >> 10]) + r.z;
        int p3 = __ldg(&g_offsets[v.w]) + __ldg(&g_blocksums[v.w >> 10]) + r.w;
        g_perm[p0] = i * 4;
        g_perm[p1] = i * 4 + 1;
        g_perm[p2] = i * 4 + 2;
        g_perm[p3] = i * 4 + 3;
    }
    if (i == 0) {
        for (int j = nq * 4; j < n; j++) {
            int v = __ldg(ids + j);
            int p = __ldg(&g_offsets[v]) + __ldg(&g_blocksums[v >> 10]) + g_rank[j];
            g_perm[p] = j;
        }
    }
}

// ---------------------------------------------------------------------------
// Pass C: gather + mean. 8 threads per vertex; thread s covers feature quad s
// as one float4 (the 8-thread group covers one 128B edge row per load).
// Per 8-edge chunk each thread loads all 8 perm entries (1 fetch + 7
// L1-broadcast hits) -> load->load address chain, no shuffle hop; the 8 row
// loads are independent (high MLP). x is streamed with L2 evict-first so the
// dense perm/offsets stay L2-resident.
// ---------------------------------------------------------------------------
__global__ void __launch_bounds__(256)
gather_kernel(const float4* __restrict__ x4, float4* __restrict__ out4,
              int V, int n_he)
{
    long long t = (long long)blockIdx.x * blockDim.x + threadIdx.x;
    int v = (int)(t >> 3);          // vertex
    int s = (int)(t & 7);           // quad index within the 32-dim row
    if (v >= V) return;

    int beg = __ldg(&g_offsets[v]) + __ldg(&g_blocksums[v >> 10]);
    int end = (v + 1 < V)
            ? __ldg(&g_offsets[v + 1]) + __ldg(&g_blocksums[(v + 1) >> 10])
            : n_he;
    int deg = end - beg;

    unsigned long long pol;
    asm("createpolicy.fractional.L2::evict_first.b64 %0, 1.0;" : "=l"(pol));

    float4 acc = make_float4(0.f, 0.f, 0.f, 0.f);

    for (int base = beg; base < end; base += 8) {
        int e[8];
        #pragma unroll
        for (int u = 0; u < 8; u++) {
            int j = base + u;
            e[u] = (j < end) ? __ldg(&g_perm[j]) : -1;
        }
        #pragma unroll
        for (int u = 0; u < 8; u++) {
            if (e[u] >= 0) {
                float4 a;
                asm("ld.global.nc.L2::cache_hint.v4.f32 {%0, %1, %2, %3}, [%4], %5;"
                    : "=f"(a.x), "=f"(a.y), "=f"(a.z), "=f"(a.w)
                    : "l"(x4 + (long long)e[u] * 8 + s), "l"(pol));
                acc.x += a.x; acc.y += a.y; acc.z += a.z; acc.w += a.w;
            }
        }
    }

    float inv = 1.0f / fmaxf((float)deg, 1.0f);
    out4[(long long)v * 8 + s] =
        make_float4(acc.x * inv, acc.y * inv, acc.z * inv, acc.w * inv);
}

extern "C" void kernel_launch(void* const* d_in, const int* in_sizes, int n_in,
                              void* d_out, int out_size)
{
    const float4* x4  = (const float4*)d_in[0];
    const int*    ids = (const int*)d_in[1];

    int n_he = in_sizes[1];                     // element count of vertex_ids
    int V    = (int)((long long)out_size / 32); // output is [V, 32]
    int nq   = n_he >> 2;                       // int4 quads in the id stream

    // Zero the histogram.
    void* counts_ptr = nullptr;
    cudaGetSymbolAddress(&counts_ptr, g_counts);
    cudaMemsetAsync(counts_ptr, 0, (size_t)V * sizeof(int));

    // Pass A: histogram + ranks (the only atomic pass).
    rank_hist_kernel<<<(nq + 255) / 256, 256>>>((const int4*)ids, nq, ids, n_he);

    // Exclusive scan: block-local offsets + global block offsets.
    int nb = (V + 1023) / 1024;
    scan1_kernel<<<nb, 1024>>>(V);
    scan2_kernel<<<1, 1024>>>(nb);

    // Pass B: atomic-free placement.
    place_kernel<<<(nq + 255) / 256, 256>>>((const int4*)ids, nq, ids, n_he);

    // Pass C: gather + mean, 8 threads per vertex.
    {
        long long total = (long long)V * 8;
        int threads = 256;
        int blocks = (int)((total + threads - 1) / threads);
        gather_kernel<<<blocks, threads>>>(x4, (float4*)d_out, V, n_he);
    }
}